// round 14
// baseline (speedup 1.0000x reference)
#include <cuda_runtime.h>
#include <math.h>
#include <stdint.h>

#define NB2  256
#define NB   128
#define TT   73
#define TF   103
#define HS   768
#define GS   2304
#define TSEG 30
#define KSPLIT 4
#define PB   144

// ---------------- scratch ----------------
__device__ float    g_raw   [NB2 * TSEG * HS];
__device__ float    g_gi    [NB2 * TF * GS];
__device__ float    g_te    [NB2 * TT * HS];
__device__ float    g_temb  [NB2 * HS];
__device__ float    g_score3[NB2 * TSEG];
__device__ float    g_causal[NB2 * TSEG];
__device__ float    g_x     [NB2 * TF * HS];
__device__ float    g_xs    [NB2 * TF * HS];
__device__ float    g_part  [KSPLIT * NB2 * GS];
__device__ float    g_feats [NB2 * HS];
__device__ float    g_diff  [NB * HS];
__device__ float    g_diffW [NB * HS];
__device__ int      g_arrive;
__device__ unsigned g_wp1 [768 * 1024];   // packed W_lin1
__device__ unsigned g_wpt [GS * HS];      // packed Wih_t
__device__ unsigned g_wpg [GS * HS];      // packed Wih_g
__device__ unsigned g_wp4 [HS * HS];      // packed W_d4

__device__ __forceinline__ unsigned f2tf(float x) {
    unsigned r;
    asm("cvt.rna.tf32.f32 %0, %1;" : "=r"(r) : "f"(x));
    return r;
}
__device__ __forceinline__ void cp16(uint32_t dst, const void* src) {
    asm volatile("cp.async.cg.shared.global [%0], [%1], 16;" :: "r"(dst), "l"(src));
}

__device__ __forceinline__ void gbar(int target) {
    __threadfence();
    __syncthreads();
    if (threadIdx.x == 0) {
        atomicAdd(&g_arrive, 1);
        while (*((volatile int*)&g_arrive) < target) __nanosleep(32);
    }
    __syncthreads();
    __threadfence();
}
__global__ void zero_arrive_k() { g_arrive = 0; }

// ---------------- weight pack: tf32 bits, k-permuted so (k,k+4) adjacent ----------------
__global__ __launch_bounds__(192) void pack_w_k(const float* __restrict__ W,
                                                unsigned* __restrict__ Wp, int K)
{
    int n = blockIdx.x;
    const float* src = W + (size_t)n * K;
    unsigned* dst = Wp + (size_t)n * K;
    for (int k = threadIdx.x; k < K; k += 192) {
        int kp = (k & ~7) | ((k & 3) << 1) | ((k & 4) >> 2);
        dst[kp] = f2tf(src[k]);
    }
}

// ---------------- TF32 GEMM: packed-B, LDS.64 B frags, cp.async double-buffered ----------------
// C = A @ W^T (+bias). A [M,K] fp32 row stride lda; Wp packed tf32 [N,K].
__global__ __launch_bounds__(128) void gemm_tf32(
    const float* __restrict__ A, int lda,
    const unsigned* __restrict__ Wp,
    const float* __restrict__ bias,
    float* __restrict__ C, int ldc, int K)
{
    extern __shared__ float dsm[];
    float    (*As)[128][36] = (float    (*)[128][36])dsm;                  // [2][128][36]
    unsigned (*Bs)[128][40] = (unsigned (*)[128][40])(dsm + 2 * 128 * 36); // [2][128][40]

    const int tid  = threadIdx.x;
    const int lane = tid & 31;
    const int wid  = tid >> 5;
    const int wm   = (wid & 1) << 6;
    const int wn   = (wid >> 1) << 6;
    const int gid  = lane >> 2;
    const int tig  = lane & 3;
    const int row0 = blockIdx.y << 7;
    const int col0 = blockIdx.x << 7;

    const float*    ap = A  + (size_t)(row0 + tid) * lda;
    const unsigned* wp = Wp + (size_t)(col0 + tid) * K;
    const uint32_t sA0 = (uint32_t)__cvta_generic_to_shared(&As[0][tid][0]);
    const uint32_t sA1 = (uint32_t)__cvta_generic_to_shared(&As[1][tid][0]);
    const uint32_t sB0 = (uint32_t)__cvta_generic_to_shared(&Bs[0][tid][0]);
    const uint32_t sB1 = (uint32_t)__cvta_generic_to_shared(&Bs[1][tid][0]);

    float acc[4][8][4];
#pragma unroll
    for (int mt = 0; mt < 4; mt++)
#pragma unroll
        for (int nt = 0; nt < 8; nt++)
#pragma unroll
            for (int q = 0; q < 4; q++) acc[mt][nt][q] = 0.f;

    const int nk = K >> 5;
#pragma unroll
    for (int j = 0; j < 8; j++) {
        cp16(sA0 + j * 16, ap + (j << 2));
        cp16(sB0 + j * 16, wp + (j << 2));
    }
    asm volatile("cp.async.commit_group;");

    for (int it = 0; it < nk; it++) {
        const int cur = it & 1;
        if (it + 1 < nk) {
            const uint32_t dA = (cur ? sA0 : sA1);
            const uint32_t dB = (cur ? sB0 : sB1);
            const float*    an  = ap + ((it + 1) << 5);
            const unsigned* wn2 = wp + ((it + 1) << 5);
#pragma unroll
            for (int j = 0; j < 8; j++) {
                cp16(dA + j * 16, an + (j << 2));
                cp16(dB + j * 16, wn2 + (j << 2));
            }
            asm volatile("cp.async.commit_group;");
            asm volatile("cp.async.wait_group 1;");
        } else {
            asm volatile("cp.async.wait_group 0;");
        }
        __syncthreads();

#pragma unroll
        for (int s = 0; s < 4; s++) {
            const int ks = s << 3;
            unsigned bf0[8], bf1[8];
#pragma unroll
            for (int nt = 0; nt < 8; nt++) {
                int cn = wn + (nt << 3) + gid;
                uint2 bb = *(const uint2*)&Bs[cur][cn][ks + (tig << 1)];
                bf0[nt] = bb.x;
                bf1[nt] = bb.y;
            }
#pragma unroll
            for (int mt = 0; mt < 4; mt++) {
                int rl = wm + (mt << 4) + gid;
                unsigned a0 = f2tf(As[cur][rl][ks + tig]);
                unsigned a1 = f2tf(As[cur][rl + 8][ks + tig]);
                unsigned a2 = f2tf(As[cur][rl][ks + tig + 4]);
                unsigned a3 = f2tf(As[cur][rl + 8][ks + tig + 4]);
#pragma unroll
                for (int nt = 0; nt < 8; nt++) {
                    asm volatile(
                        "mma.sync.aligned.m16n8k8.row.col.f32.tf32.tf32.f32 "
                        "{%0,%1,%2,%3}, {%4,%5,%6,%7}, {%8,%9}, {%0,%1,%2,%3};"
                        : "+f"(acc[mt][nt][0]), "+f"(acc[mt][nt][1]),
                          "+f"(acc[mt][nt][2]), "+f"(acc[mt][nt][3])
                        : "r"(a0), "r"(a1), "r"(a2), "r"(a3),
                          "r"(bf0[nt]), "r"(bf1[nt]));
                }
            }
        }
        __syncthreads();
    }

#pragma unroll
    for (int mt = 0; mt < 4; mt++) {
        int r0 = row0 + wm + (mt << 4) + gid;
#pragma unroll
        for (int nt = 0; nt < 8; nt++) {
            int cc = col0 + wn + (nt << 3) + (tig << 1);
            float bx = 0.f, by = 0.f;
            if (bias) { bx = bias[cc]; by = bias[cc + 1]; }
            float2 lo = make_float2(acc[mt][nt][0] + bx, acc[mt][nt][1] + by);
            float2 hi = make_float2(acc[mt][nt][2] + bx, acc[mt][nt][3] + by);
            *(float2*)&C[(size_t)r0 * ldc + cc]       = lo;
            *(float2*)&C[(size_t)(r0 + 8) * ldc + cc] = hi;
        }
    }
}
#define GEMM_SMEM ((2 * 128 * 36 + 2 * 128 * 40) * 4)

// ---------------- persistent GRU: packed-B smem slab, grid barrier per phase ----------------
__global__ __launch_bounds__(128) void gru_persist(
    float* __restrict__ seq, int T,
    const float* __restrict__ Whh,
    const float* __restrict__ gi,
    const float* __restrict__ bhh)
{
    extern __shared__ float dsm[];
    unsigned (*Bs)[200]  = (unsigned (*)[200])dsm;                      // [128][200]
    float (*As)[128][36] = (float (*)[128][36])(dsm + 128 * 200);       // [2][128][36]

    const int tid  = threadIdx.x;
    const int lane = tid & 31;
    const int wid  = tid >> 5;
    const int wm   = (wid & 1) << 6;
    const int wn   = (wid >> 1) << 6;
    const int gid  = lane >> 2;
    const int tig  = lane & 3;

    const int bid = blockIdx.x;
    const int kz  = bid / 36;
    const int r36 = bid - kz * 36;
    const int cx  = r36 >> 1;
    const int ry  = r36 & 1;
    const int col0 = cx << 7;
    const int row0 = ry << 7;
    const int kb   = kz * 192;

    // one-time: load B slab row (192 floats), then cvt + within-8 permute in place
    {
        const float* wrow = Whh + (size_t)(col0 + tid) * HS + kb;
        uint32_t bdst = (uint32_t)__cvta_generic_to_shared(&Bs[tid][0]);
#pragma unroll
        for (int j = 0; j < 48; j++)
            cp16(bdst + j * 16, wrow + (j << 2));
        asm volatile("cp.async.commit_group;");
        asm volatile("cp.async.wait_group 0;");
        unsigned* ur = (unsigned*)&Bs[tid][0];
        float*    fr = (float*)ur;
        for (int g = 0; g < 24; g++) {
            float v[8];
#pragma unroll
            for (int i = 0; i < 8; i++) v[i] = fr[g * 8 + i];
#pragma unroll
            for (int i = 0; i < 8; i++) {
                int p = ((i & 3) << 1) | ((i & 4) >> 2);
                ur[g * 8 + p] = f2tf(v[i]);
            }
        }
    }
    __syncthreads();

    const float* ap = seq + (size_t)(row0 + tid) * T * HS + kb;
    const uint32_t sA0 = (uint32_t)__cvta_generic_to_shared(&As[0][tid][0]);
    const uint32_t sA1 = (uint32_t)__cvta_generic_to_shared(&As[1][tid][0]);
    float* Pbase = g_part + ((size_t)kz * NB2 + row0) * GS + col0;

    int barid = 0;
    for (int t = 1; t < T; t++) {
        const float* a_t = ap + (size_t)(t - 1) * HS;

        float acc[4][8][4];
#pragma unroll
        for (int mt = 0; mt < 4; mt++)
#pragma unroll
            for (int nt = 0; nt < 8; nt++)
#pragma unroll
                for (int q = 0; q < 4; q++) acc[mt][nt][q] = 0.f;

#pragma unroll
        for (int j = 0; j < 8; j++) cp16(sA0 + j * 16, a_t + (j << 2));
        asm volatile("cp.async.commit_group;");

        for (int it = 0; it < 6; it++) {
            const int cur = it & 1;
            if (it + 1 < 6) {
                const uint32_t dA = (cur ? sA0 : sA1);
                const float* an = a_t + ((it + 1) << 5);
#pragma unroll
                for (int j = 0; j < 8; j++) cp16(dA + j * 16, an + (j << 2));
                asm volatile("cp.async.commit_group;");
                asm volatile("cp.async.wait_group 1;");
            } else {
                asm volatile("cp.async.wait_group 0;");
            }
            __syncthreads();

#pragma unroll
            for (int s = 0; s < 4; s++) {
                const int kloc = (it << 5) + (s << 3);
                unsigned bf0[8], bf1[8];
#pragma unroll
                for (int nt = 0; nt < 8; nt++) {
                    int cn = wn + (nt << 3) + gid;
                    uint2 bb = *(const uint2*)&Bs[cn][kloc + (tig << 1)];
                    bf0[nt] = bb.x;
                    bf1[nt] = bb.y;
                }
                const int ks = s << 3;
#pragma unroll
                for (int mt = 0; mt < 4; mt++) {
                    int rl = wm + (mt << 4) + gid;
                    unsigned a0 = f2tf(As[cur][rl][ks + tig]);
                    unsigned a1 = f2tf(As[cur][rl + 8][ks + tig]);
                    unsigned a2 = f2tf(As[cur][rl][ks + tig + 4]);
                    unsigned a3 = f2tf(As[cur][rl + 8][ks + tig + 4]);
#pragma unroll
                    for (int nt = 0; nt < 8; nt++) {
                        asm volatile(
                            "mma.sync.aligned.m16n8k8.row.col.f32.tf32.tf32.f32 "
                            "{%0,%1,%2,%3}, {%4,%5,%6,%7}, {%8,%9}, {%0,%1,%2,%3};"
                            : "+f"(acc[mt][nt][0]), "+f"(acc[mt][nt][1]),
                              "+f"(acc[mt][nt][2]), "+f"(acc[mt][nt][3])
                            : "r"(a0), "r"(a1), "r"(a2), "r"(a3),
                              "r"(bf0[nt]), "r"(bf1[nt]));
                    }
                }
            }
            __syncthreads();
        }

#pragma unroll
        for (int mt = 0; mt < 4; mt++) {
            int rr = wm + (mt << 4) + gid;
#pragma unroll
            for (int nt = 0; nt < 8; nt++) {
                int cc = wn + (nt << 3) + (tig << 1);
                *(float2*)&Pbase[(size_t)rr * GS + cc] =
                    make_float2(acc[mt][nt][0], acc[mt][nt][1]);
                *(float2*)&Pbase[(size_t)(rr + 8) * GS + cc] =
                    make_float2(acc[mt][nt][2], acc[mt][nt][3]);
            }
        }

        barid++; gbar(barid * PB);

#pragma unroll
        for (int j = 0; j < 3; j++) {
            int idx = bid * 128 + tid + j * (PB * 128);
            if (idx < NB2 * 192) {
                int b = idx / 192;
                int c = (idx - b * 192) << 2;
                float4 sr = make_float4(0, 0, 0, 0), sz = sr, sn = sr;
#pragma unroll
                for (int z = 0; z < KSPLIT; z++) {
                    const float* P = g_part + ((size_t)z * NB2 + b) * GS;
                    float4 pr = *(const float4*)(P + c);
                    float4 pz = *(const float4*)(P + 768 + c);
                    float4 pn = *(const float4*)(P + 1536 + c);
                    sr.x += pr.x; sr.y += pr.y; sr.z += pr.z; sr.w += pr.w;
                    sz.x += pz.x; sz.y += pz.y; sz.z += pz.z; sz.w += pz.w;
                    sn.x += pn.x; sn.y += pn.y; sn.z += pn.z; sn.w += pn.w;
                }
                float4 hp = *(const float4*)(seq + (size_t)b * T * HS + (size_t)(t - 1) * HS + c);
                float4 br = *(const float4*)(bhh + c);
                float4 bz = *(const float4*)(bhh + 768 + c);
                float4 bn = *(const float4*)(bhh + 1536 + c);
                const float* gip = gi + (size_t)b * T * GS + (size_t)t * GS;
                float4 ir  = *(const float4*)(gip + c);
                float4 iz  = *(const float4*)(gip + 768 + c);
                float4 inn = *(const float4*)(gip + 1536 + c);
                float4 h;
                {
                    float rg = 1.f / (1.f + expf(-(ir.x + sr.x + br.x)));
                    float zg = 1.f / (1.f + expf(-(iz.x + sz.x + bz.x)));
                    float ng = tanhf(inn.x + rg * (sn.x + bn.x));
                    h.x = (1.f - zg) * ng + zg * hp.x;
                }
                {
                    float rg = 1.f / (1.f + expf(-(ir.y + sr.y + br.y)));
                    float zg = 1.f / (1.f + expf(-(iz.y + sz.y + bz.y)));
                    float ng = tanhf(inn.y + rg * (sn.y + bn.y));
                    h.y = (1.f - zg) * ng + zg * hp.y;
                }
                {
                    float rg = 1.f / (1.f + expf(-(ir.z + sr.z + br.z)));
                    float zg = 1.f / (1.f + expf(-(iz.z + sz.z + bz.z)));
                    float ng = tanhf(inn.z + rg * (sn.z + bn.z));
                    h.z = (1.f - zg) * ng + zg * hp.z;
                }
                {
                    float rg = 1.f / (1.f + expf(-(ir.w + sr.w + br.w)));
                    float zg = 1.f / (1.f + expf(-(iz.w + sz.w + bz.w)));
                    float ng = tanhf(inn.w + rg * (sn.w + bn.w));
                    h.w = (1.f - zg) * ng + zg * hp.w;
                }
                *(float4*)(seq + (size_t)b * T * HS + (size_t)t * HS + c) = h;
            }
        }

        barid++; gbar(barid * PB);
    }
}
#define PERSIST_SMEM (128 * 200 * 4 + 2 * 128 * 36 * 4)

// ---------------- GRU t=0 epilogue ----------------
__global__ __launch_bounds__(256) void gru_epi0(
    const float* __restrict__ gi, int T,
    const float* __restrict__ bhh, float* __restrict__ seq)
{
    int idx = blockIdx.x * 256 + threadIdx.x;
    int b = idx / 192;
    int c = (idx - b * 192) << 2;

    float4 br = *(const float4*)(bhh + c);
    float4 bz = *(const float4*)(bhh + 768 + c);
    float4 bn = *(const float4*)(bhh + 1536 + c);
    const float* gip = gi + (size_t)b * T * GS;
    float4 ir  = *(const float4*)(gip + c);
    float4 iz  = *(const float4*)(gip + 768 + c);
    float4 inn = *(const float4*)(gip + 1536 + c);

    float4 h;
    { float r = 1.f/(1.f+expf(-(ir.x+br.x))); float z = 1.f/(1.f+expf(-(iz.x+bz.x)));
      h.x = (1.f-z)*tanhf(inn.x + r*bn.x); }
    { float r = 1.f/(1.f+expf(-(ir.y+br.y))); float z = 1.f/(1.f+expf(-(iz.y+bz.y)));
      h.y = (1.f-z)*tanhf(inn.y + r*bn.y); }
    { float r = 1.f/(1.f+expf(-(ir.z+br.z))); float z = 1.f/(1.f+expf(-(iz.z+bz.z)));
      h.z = (1.f-z)*tanhf(inn.z + r*bn.z); }
    { float r = 1.f/(1.f+expf(-(ir.w+br.w))); float z = 1.f/(1.f+expf(-(iz.w+bz.w)));
      h.w = (1.f-z)*tanhf(inn.w + r*bn.w); }
    *(float4*)(seq + (size_t)b * T * HS + c) = h;
}

// ---------------- text_embed ----------------
__global__ __launch_bounds__(192) void text_embed_k(const float* __restrict__ wdt,
                                                    const float* __restrict__ bdt)
{
    int j = blockIdx.x;
    int h4 = threadIdx.x;
    const float* base = g_te + (size_t)j * TT * HS + (h4 << 2);
    float4 acc = make_float4(bdt[0], bdt[0], bdt[0], bdt[0]);
    for (int t = 0; t < TT; t++) {
        float4 v = *(const float4*)(base + (size_t)t * HS);
        float w = wdt[t];
        acc.x = fmaf(v.x, w, acc.x); acc.y = fmaf(v.y, w, acc.y);
        acc.z = fmaf(v.z, w, acc.z); acc.w = fmaf(v.w, w, acc.w);
    }
    *(float4*)&g_temb[(size_t)j * HS + (h4 << 2)] = acc;
}

// ---------------- attention ----------------
__global__ __launch_bounds__(256) void attn_k(const float* __restrict__ wd3)
{
    __shared__ float cv[HS];
    __shared__ float tb[HS];
    __shared__ float sc[3][TSEG];
    int j = blockIdx.x;
    int tid = threadIdx.x;
    const float* rawj = g_raw + (size_t)j * TSEG * HS;

    for (int h = tid; h < HS; h += 256) {
        float s = 0.f;
        for (int t = 0; t < TSEG; t++) s += rawj[(size_t)t * HS + h];
        cv[h] = s * (1.f / TSEG);
        tb[h] = g_temb[(size_t)j * HS + h];
    }
    __syncthreads();

    int t = tid >> 3;
    int lane = tid & 7;
    float s1 = 0.f, s2 = 0.f, s3 = 0.f;
    if (t < TSEG) {
        const float* rp = rawj + (size_t)t * HS;
        for (int h = lane; h < HS; h += 8) {
            float v = rp[h];
            s1 = fmaf(v, tb[h], s1);
            s2 = fmaf(v, cv[h], s2);
            s3 = fmaf(v, wd3[h], s3);
        }
    }
#pragma unroll
    for (int o = 4; o; o >>= 1) {
        s1 += __shfl_down_sync(0xffffffffu, s1, o, 8);
        s2 += __shfl_down_sync(0xffffffffu, s2, o, 8);
        s3 += __shfl_down_sync(0xffffffffu, s3, o, 8);
    }
    if (t < TSEG && lane == 0) {
        sc[0][t] = s1; sc[1][t] = s2; sc[2][t] = s3;
        g_score3[j * TSEG + t] = s3;
    }
    __syncthreads();

    if (tid == 0) {
        float tot[TSEG];
        for (int q = 0; q < TSEG; q++) tot[q] = 0.f;
        for (int s = 0; s < 3; s++) {
            float mx = sc[s][0];
            for (int q = 1; q < TSEG; q++) mx = fmaxf(mx, sc[s][q]);
            float sum = 0.f;
            float e[TSEG];
            for (int q = 0; q < TSEG; q++) { e[q] = expf(sc[s][q] - mx); sum += e[q]; }
            float inv = 1.f / sum;
            for (int q = 0; q < TSEG; q++) tot[q] += e[q] * inv;
        }
        for (int q = 0; q < TSEG; q++) g_causal[j * TSEG + q] = tot[q];
    }
}

// ---------------- build fused sequence ----------------
__global__ __launch_bounds__(192) void build_x_k(
    const float* __restrict__ text, const float* __restrict__ pos_text,
    const float* __restrict__ wd2, const float* __restrict__ bd2)
{
    int t = blockIdx.x;
    int j = blockIdx.y;
    int h = threadIdx.x << 2;
    float4 v;
    if (t < TSEG) {
        float c = g_causal[j * TSEG + t];
        float4 r  = *(const float4*)&g_raw[(size_t)j * TSEG * HS + (size_t)t * HS + h];
        float4 w2 = *(const float4*)&wd2[h];
        float4 b2 = *(const float4*)&bd2[h];
        v.x = r.x * fmaf(c, w2.x, b2.x);
        v.y = r.y * fmaf(c, w2.y, b2.y);
        v.z = r.z * fmaf(c, w2.z, b2.z);
        v.w = r.w * fmaf(c, w2.w, b2.w);
    } else {
        int tt = t - TSEG;
        const float* src = (j < NB)
            ? text     + (size_t)j        * TT * HS + (size_t)tt * HS + h
            : pos_text + (size_t)(j - NB) * TT * HS + (size_t)tt * HS + h;
        v = *(const float4*)src;
    }
    *(float4*)&g_x[(size_t)j * TF * HS + (size_t)t * HS + h] = v;
}

// ---------------- feats ----------------
__global__ __launch_bounds__(192) void feats_k(const float* __restrict__ wc1,
                                               const float* __restrict__ bc1)
{
    int j = blockIdx.x;
    int h = threadIdx.x << 2;
    const float* base = g_xs + (size_t)j * TF * HS + h;
    float4 acc = make_float4(bc1[0], bc1[0], bc1[0], bc1[0]);
    for (int t = 0; t < TF; t++) {
        float4 v = *(const float4*)(base + (size_t)t * HS);
        float w = wc1[t];
        acc.x = fmaf(v.x, w, acc.x); acc.y = fmaf(v.y, w, acc.y);
        acc.z = fmaf(v.z, w, acc.z); acc.w = fmaf(v.w, w, acc.w);
    }
    acc.x = acc.x >= 0.f ? acc.x : 0.01f * acc.x;
    acc.y = acc.y >= 0.f ? acc.y : 0.01f * acc.y;
    acc.z = acc.z >= 0.f ? acc.z : 0.01f * acc.z;
    acc.w = acc.w >= 0.f ? acc.w : 0.01f * acc.w;
    *(float4*)&g_feats[(size_t)j * HS + h] = acc;
}

// ---------------- pred ----------------
__global__ __launch_bounds__(256) void pred_k(const float* __restrict__ wc2,
                                              const float* __restrict__ bc2,
                                              float* __restrict__ out)
{
    int j = blockIdx.x;
    int warp = threadIdx.x >> 5;
    int lane = threadIdx.x & 31;
    const float* f = g_feats + (size_t)j * HS;
    for (int o = warp; o < 20; o += 8) {
        const float* w = wc2 + (size_t)o * HS;
        float s = 0.f;
        for (int k = lane; k < HS; k += 32) s = fmaf(f[k], w[k], s);
#pragma unroll
        for (int d = 16; d; d >>= 1) s += __shfl_down_sync(0xffffffffu, s, d);
        if (lane == 0) out[j * 20 + o] = s + bc2[o];
    }
}

// ---------------- top-10 gather ----------------
__global__ __launch_bounds__(192) void topk_k()
{
    __shared__ int idxA[10], idxB[10];
    int b = blockIdx.x;
    int tid = threadIdx.x;
    if (tid < 2) {
        const float* sp = g_score3 + (size_t)(tid == 0 ? b : b + NB) * TSEG;
        float v[TSEG];
        for (int q = 0; q < TSEG; q++) v[q] = sp[q];
        int* dst = (tid == 0) ? idxA : idxB;
        for (int k = 0; k < 10; k++) {
            float best = -1e38f; int bi = 0;
            for (int q = 0; q < TSEG; q++)
                if (v[q] > best) { best = v[q]; bi = q; }
            dst[k] = bi;
            v[bi] = -1e38f;
        }
    }
    __syncthreads();
    int h = tid << 2;
    const float* A  = g_raw + (size_t)b * TSEG * HS + h;
    const float* Bm = g_raw + (size_t)(b + NB) * TSEG * HS + h;
    float4 sa = make_float4(0, 0, 0, 0), sb = make_float4(0, 0, 0, 0);
#pragma unroll
    for (int k = 0; k < 10; k++) {
        float4 a = *(const float4*)(A  + (size_t)idxA[k] * HS);
        float4 c = *(const float4*)(Bm + (size_t)idxB[k] * HS);
        sa.x += a.x; sa.y += a.y; sa.z += a.z; sa.w += a.w;
        sb.x += c.x; sb.y += c.y; sb.z += c.z; sb.w += c.w;
    }
    float4 d = make_float4((sa.x - sb.x) * 0.1f, (sa.y - sb.y) * 0.1f,
                           (sa.z - sb.z) * 0.1f, (sa.w - sb.w) * 0.1f);
    *(float4*)&g_diff[(size_t)b * HS + h] = d;
}

// ---------------- loss ----------------
__global__ __launch_bounds__(1024) void loss_k(float* __restrict__ out, int out_size)
{
    __shared__ float red[32];
    int tid = threadIdx.x;
    float s = 0.f;
    for (int i = tid; i < NB * HS; i += 1024) {
        float d = g_diffW[i];
        s = fmaf(d, d, s);
    }
#pragma unroll
    for (int d = 16; d; d >>= 1) s += __shfl_down_sync(0xffffffffu, s, d);
    if ((tid & 31) == 0) red[tid >> 5] = s;
    __syncthreads();
    if (tid < 32) {
        float v = red[tid];
#pragma unroll
        for (int d = 16; d; d >>= 1) v += __shfl_down_sync(0xffffffffu, v, d);
        if (tid == 0 && out_size > NB2 * 20)
            out[NB2 * 20] = v * (1.f / (NB * HS));
    }
}

// ---------------- host launcher ----------------
extern "C" void kernel_launch(void* const* d_in, const int* in_sizes, int n_in,
                              void* d_out, int out_size)
{
    const float* s3d      = (const float*)d_in[0];
    const float* text     = (const float*)d_in[1];
    const float* pos_s3d  = (const float*)d_in[2];
    const float* pos_text = (const float*)d_in[3];
    const float* W_lin1 = (const float*)d_in[4];
    const float* b_lin1 = (const float*)d_in[5];
    const float* Wih_t  = (const float*)d_in[6];
    const float* Whh_t  = (const float*)d_in[7];
    const float* bih_t  = (const float*)d_in[8];
    const float* bhh_t  = (const float*)d_in[9];
    const float* W_dt   = (const float*)d_in[10];
    const float* b_dt   = (const float*)d_in[11];
    const float* W_d3   = (const float*)d_in[12];
    const float* W_d2   = (const float*)d_in[14];
    const float* b_d2   = (const float*)d_in[15];
    const float* Wih_g  = (const float*)d_in[16];
    const float* Whh_g  = (const float*)d_in[17];
    const float* bih_g  = (const float*)d_in[18];
    const float* bhh_g  = (const float*)d_in[19];
    const float* W_c1   = (const float*)d_in[20];
    const float* b_c1   = (const float*)d_in[21];
    const float* W_c2   = (const float*)d_in[22];
    const float* b_c2   = (const float*)d_in[23];
    const float* W_d4   = (const float*)d_in[24];
    float* out = (float*)d_out;

    float *p_raw, *p_gi, *p_te, *p_x, *p_xs, *p_diff, *p_diffW;
    unsigned *p_wp1, *p_wpt, *p_wpg, *p_wp4;
    cudaGetSymbolAddress((void**)&p_raw,   g_raw);
    cudaGetSymbolAddress((void**)&p_gi,    g_gi);
    cudaGetSymbolAddress((void**)&p_te,    g_te);
    cudaGetSymbolAddress((void**)&p_x,     g_x);
    cudaGetSymbolAddress((void**)&p_xs,    g_xs);
    cudaGetSymbolAddress((void**)&p_diff,  g_diff);
    cudaGetSymbolAddress((void**)&p_diffW, g_diffW);
    cudaGetSymbolAddress((void**)&p_wp1,   g_wp1);
    cudaGetSymbolAddress((void**)&p_wpt,   g_wpt);
    cudaGetSymbolAddress((void**)&p_wpg,   g_wpg);
    cudaGetSymbolAddress((void**)&p_wp4,   g_wp4);

    // idempotent; no static guards allowed
    cudaFuncSetAttribute(gemm_tf32,  cudaFuncAttributeMaxDynamicSharedMemorySize, GEMM_SMEM);
    cudaFuncSetAttribute(gru_persist, cudaFuncAttributeMaxDynamicSharedMemorySize, PERSIST_SMEM);

    // 0) pack weights (tf32 + k-permutation)
    pack_w_k<<<768, 192>>>(W_lin1, p_wp1, 1024);
    pack_w_k<<<GS,  192>>>(Wih_t,  p_wpt, 768);
    pack_w_k<<<GS,  192>>>(Wih_g,  p_wpg, 768);
    pack_w_k<<<768, 192>>>(W_d4,   p_wp4, 768);

    // 1) lin1: A and Bm into raw_img (M=3840 each, N=768, K=1024)
    gemm_tf32<<<dim3(6, 30), 128, GEMM_SMEM>>>(s3d,     1024, p_wp1, b_lin1, p_raw,              768, 1024);
    gemm_tf32<<<dim3(6, 30), 128, GEMM_SMEM>>>(pos_s3d, 1024, p_wp1, b_lin1, p_raw + 3840 * 768, 768, 1024);

    // 2) text GRU input projection (M=9344 each, N=2304, K=768)
    gemm_tf32<<<dim3(18, 73), 128, GEMM_SMEM>>>(text,     768, p_wpt, bih_t, p_gi,                     GS, 768);
    gemm_tf32<<<dim3(18, 73), 128, GEMM_SMEM>>>(pos_text, 768, p_wpt, bih_t, p_gi + (size_t)9344 * GS, GS, 768);

    // 3) text GRU: t=0 epilogue, then persistent kernel for t=1..72
    gru_epi0<<<192, 256>>>(p_gi, TT, bhh_t, p_te);
    zero_arrive_k<<<1, 1>>>();
    gru_persist<<<PB, 128, PERSIST_SMEM>>>(p_te, TT, Whh_t, p_gi, bhh_t);

    // 4) text_embed, attention, fused-sequence assembly
    text_embed_k<<<NB2, 192>>>(W_dt, b_dt);
    attn_k<<<NB2, 256>>>(W_d3);
    build_x_k<<<dim3(TF, NB2), 192>>>(text, pos_text, W_d2, b_d2);

    // 5) fusion GRU input projection (M=26368, N=2304, K=768)
    gemm_tf32<<<dim3(18, 206), 128, GEMM_SMEM>>>(p_x, 768, p_wpg, bih_g, p_gi, GS, 768);

    // 6) fusion GRU: t=0 epilogue, then persistent kernel for t=1..102
    gru_epi0<<<192, 256>>>(p_gi, TF, bhh_g, p_xs);
    zero_arrive_k<<<1, 1>>>();
    gru_persist<<<PB, 128, PERSIST_SMEM>>>(p_xs, TF, Whh_g, p_gi, bhh_g);

    // 7) classifier
    feats_k<<<NB2, 192>>>(W_c1, b_c1);
    pred_k<<<NB2, 256>>>(W_c2, b_c2, out);

    // 8) top-10 gather + loss
    topk_k<<<NB, 192>>>();
    gemm_tf32<<<dim3(6, 1), 128, GEMM_SMEM>>>(p_diff, 768, p_wp4, nullptr, p_diffW, 768, 768);
    loss_k<<<1, 1024>>>(out, out_size);
}

// round 17
// speedup vs baseline: 1.0604x; 1.0604x over previous
#include <cuda_runtime.h>
#include <math.h>
#include <stdint.h>

#define NB2  256
#define NB   128
#define TT   73
#define TF   103
#define HS   768
#define GS   2304
#define TSEG 30
#define KSPLIT 4
#define PB   144     // persistent blocks; <=148 SMs -> all resident

// ---------------- scratch ----------------
__device__ float g_raw   [NB2 * TSEG * HS];
__device__ float g_gi    [NB2 * TF * GS];
__device__ float g_te    [NB2 * TT * HS];
__device__ float g_temb  [NB2 * HS];
__device__ float g_score3[NB2 * TSEG];
__device__ float g_causal[NB2 * TSEG];
__device__ float g_x     [NB2 * TF * HS];
__device__ float g_xs    [NB2 * TF * HS];
__device__ float g_part  [KSPLIT * NB2 * GS];
__device__ float g_feats [NB2 * HS];
__device__ float g_diff  [NB * HS];
__device__ float g_diffW [NB * HS];
__device__ int   g_arrive;

__device__ __forceinline__ unsigned f2tf(float x) {
    unsigned r;
    asm("cvt.rna.tf32.f32 %0, %1;" : "=r"(r) : "f"(x));
    return r;
}
__device__ __forceinline__ void cp16(uint32_t dst, const void* src) {
    asm volatile("cp.async.cg.shared.global [%0], [%1], 16;" :: "r"(dst), "l"(src));
}

// grid-wide barrier on monotonic counter; target = barrier_index * PB.
__device__ __forceinline__ void gbar(int target) {
    __threadfence();
    __syncthreads();
    if (threadIdx.x == 0) {
        atomicAdd(&g_arrive, 1);
        while (*((volatile int*)&g_arrive) < target) __nanosleep(32);
    }
    __syncthreads();
    __threadfence();
}
__global__ void zero_arrive_k() { g_arrive = 0; }

// ---------------- TF32 tensor-core GEMM, cp.async double-buffered ----------------
// C = A @ W^T (+bias). Block 128x128, 4 warps (2x2), warp 64x64, mma.m16n8k8.tf32.
__global__ __launch_bounds__(128) void gemm_tf32(
    const float* __restrict__ A, int lda,
    const float* __restrict__ W, int ldw,
    const float* __restrict__ bias,
    float* __restrict__ C, int ldc, int K)
{
    extern __shared__ float dsm[];
    float (*As)[128][36] = (float (*)[128][36])dsm;
    float (*Bs)[128][36] = (float (*)[128][36])(dsm + 2 * 128 * 36);

    const int tid  = threadIdx.x;
    const int lane = tid & 31;
    const int wid  = tid >> 5;
    const int wm   = (wid & 1) << 6;
    const int wn   = (wid >> 1) << 6;
    const int gid  = lane >> 2;
    const int tig  = lane & 3;
    const int row0 = blockIdx.y << 7;
    const int col0 = blockIdx.x << 7;

    const float* ap = A + (size_t)(row0 + tid) * lda;
    const float* wp = W + (size_t)(col0 + tid) * ldw;
    const uint32_t sA0 = (uint32_t)__cvta_generic_to_shared(&As[0][tid][0]);
    const uint32_t sA1 = (uint32_t)__cvta_generic_to_shared(&As[1][tid][0]);
    const uint32_t sB0 = (uint32_t)__cvta_generic_to_shared(&Bs[0][tid][0]);
    const uint32_t sB1 = (uint32_t)__cvta_generic_to_shared(&Bs[1][tid][0]);

    float acc[4][8][4];
#pragma unroll
    for (int mt = 0; mt < 4; mt++)
#pragma unroll
        for (int nt = 0; nt < 8; nt++)
#pragma unroll
            for (int q = 0; q < 4; q++) acc[mt][nt][q] = 0.f;

    const int nk = K >> 5;
#pragma unroll
    for (int j = 0; j < 8; j++) {
        cp16(sA0 + j * 16, ap + (j << 2));
        cp16(sB0 + j * 16, wp + (j << 2));
    }
    asm volatile("cp.async.commit_group;");

    for (int it = 0; it < nk; it++) {
        const int cur = it & 1;
        if (it + 1 < nk) {
            const uint32_t dA = (cur ? sA0 : sA1);
            const uint32_t dB = (cur ? sB0 : sB1);
            const float* an  = ap + ((it + 1) << 5);
            const float* wn2 = wp + ((it + 1) << 5);
#pragma unroll
            for (int j = 0; j < 8; j++) {
                cp16(dA + j * 16, an + (j << 2));
                cp16(dB + j * 16, wn2 + (j << 2));
            }
            asm volatile("cp.async.commit_group;");
            asm volatile("cp.async.wait_group 1;");
        } else {
            asm volatile("cp.async.wait_group 0;");
        }
        __syncthreads();

#pragma unroll
        for (int s = 0; s < 4; s++) {
            const int ks = s << 3;
            unsigned bf0[8], bf1[8];
#pragma unroll
            for (int nt = 0; nt < 8; nt++) {
                int cn = wn + (nt << 3) + gid;
                bf0[nt] = f2tf(Bs[cur][cn][ks + tig]);
                bf1[nt] = f2tf(Bs[cur][cn][ks + tig + 4]);
            }
#pragma unroll
            for (int mt = 0; mt < 4; mt++) {
                int rl = wm + (mt << 4) + gid;
                unsigned a0 = f2tf(As[cur][rl][ks + tig]);
                unsigned a1 = f2tf(As[cur][rl + 8][ks + tig]);
                unsigned a2 = f2tf(As[cur][rl][ks + tig + 4]);
                unsigned a3 = f2tf(As[cur][rl + 8][ks + tig + 4]);
#pragma unroll
                for (int nt = 0; nt < 8; nt++) {
                    asm volatile(
                        "mma.sync.aligned.m16n8k8.row.col.f32.tf32.tf32.f32 "
                        "{%0,%1,%2,%3}, {%4,%5,%6,%7}, {%8,%9}, {%0,%1,%2,%3};"
                        : "+f"(acc[mt][nt][0]), "+f"(acc[mt][nt][1]),
                          "+f"(acc[mt][nt][2]), "+f"(acc[mt][nt][3])
                        : "r"(a0), "r"(a1), "r"(a2), "r"(a3),
                          "r"(bf0[nt]), "r"(bf1[nt]));
                }
            }
        }
        __syncthreads();
    }

#pragma unroll
    for (int mt = 0; mt < 4; mt++) {
        int r0 = row0 + wm + (mt << 4) + gid;
#pragma unroll
        for (int nt = 0; nt < 8; nt++) {
            int cc = col0 + wn + (nt << 3) + (tig << 1);
            float bx = 0.f, by = 0.f;
            if (bias) { bx = bias[cc]; by = bias[cc + 1]; }
            float2 lo = make_float2(acc[mt][nt][0] + bx, acc[mt][nt][1] + by);
            float2 hi = make_float2(acc[mt][nt][2] + bx, acc[mt][nt][3] + by);
            *(float2*)&C[(size_t)r0 * ldc + cc]       = lo;
            *(float2*)&C[(size_t)(r0 + 8) * ldc + cc] = hi;
        }
    }
}
#define GEMM_SMEM (2 * 2 * 128 * 36 * 4)

// ---------------- persistent GRU, 256 threads (8 warps) per block ----------------
// Block b = (kz*36 + cx*2 + ry). Warp grid 4x2 over the 128x128 tile (warp = 32x64).
// B slab (128 x 192 of Whh) cached in smem as tf32 bits, stride 196 (conflict-free).
__global__ __launch_bounds__(256) void gru_persist(
    float* __restrict__ seq, int T,
    const float* __restrict__ Whh,
    const float* __restrict__ gi,
    const float* __restrict__ bhh)
{
    extern __shared__ float dsm[];
    unsigned (*Bs)[196]  = (unsigned (*)[196])dsm;                      // [128][196]
    float (*As)[128][36] = (float (*)[128][36])(dsm + 128 * 196);       // [2][128][36]

    const int tid  = threadIdx.x;
    const int lane = tid & 31;
    const int wid  = tid >> 5;           // 0..7
    const int wm   = (wid & 3) << 5;     // 0/32/64/96
    const int wn   = (wid >> 2) << 6;    // 0/64
    const int gid  = lane >> 2;
    const int tig  = lane & 3;

    const int bid = blockIdx.x;
    const int kz  = bid / 36;
    const int r36 = bid - kz * 36;
    const int cx  = r36 >> 1;
    const int ry  = r36 & 1;
    const int col0 = cx << 7;
    const int row0 = ry << 7;
    const int kb   = kz * 192;

    // one-time: load + convert B slab. Thread owns half a row: row=tid>>1, 96 floats.
    {
        const int brow = tid >> 1;
        const int bo   = (tid & 1) * 96;
        const float* wrow = Whh + (size_t)(col0 + brow) * HS + kb + bo;
        uint32_t bdst = (uint32_t)__cvta_generic_to_shared(&Bs[brow][bo]);
#pragma unroll
        for (int j = 0; j < 24; j++)
            cp16(bdst + j * 16, wrow + (j << 2));
        asm volatile("cp.async.commit_group;");
        asm volatile("cp.async.wait_group 0;");
        unsigned* ur = (unsigned*)&Bs[brow][bo];
        float*    fr = (float*)ur;
#pragma unroll 8
        for (int i = 0; i < 96; i++) {
            float v = fr[i];
            ur[i] = f2tf(v);
        }
    }
    __syncthreads();

    // A staging: row = tid>>1, k-half = (tid&1)*16; 4 cp16 per k-tile.
    const int ar = tid >> 1;
    const int ak = (tid & 1) << 4;
    const float* ap = seq + (size_t)(row0 + ar) * T * HS + kb + ak;
    const uint32_t sA0 = (uint32_t)__cvta_generic_to_shared(&As[0][ar][ak]);
    const uint32_t sA1 = (uint32_t)__cvta_generic_to_shared(&As[1][ar][ak]);
    float* Pbase = g_part + ((size_t)kz * NB2 + row0) * GS + col0;

    int barid = 0;
    for (int t = 1; t < T; t++) {
        const float* a_t = ap + (size_t)(t - 1) * HS;

        float acc[2][8][4];
#pragma unroll
        for (int mt = 0; mt < 2; mt++)
#pragma unroll
            for (int nt = 0; nt < 8; nt++)
#pragma unroll
                for (int q = 0; q < 4; q++) acc[mt][nt][q] = 0.f;

        // phase A: partial gemm over 6 k-tiles, A double-buffered
#pragma unroll
        for (int j = 0; j < 4; j++) cp16(sA0 + j * 16, a_t + (j << 2));
        asm volatile("cp.async.commit_group;");

        for (int it = 0; it < 6; it++) {
            const int cur = it & 1;
            if (it + 1 < 6) {
                const uint32_t dA = (cur ? sA0 : sA1);
                const float* an = a_t + ((it + 1) << 5);
#pragma unroll
                for (int j = 0; j < 4; j++) cp16(dA + j * 16, an + (j << 2));
                asm volatile("cp.async.commit_group;");
                asm volatile("cp.async.wait_group 1;");
            } else {
                asm volatile("cp.async.wait_group 0;");
            }
            __syncthreads();

#pragma unroll
            for (int s = 0; s < 4; s++) {
                const int kloc = (it << 5) + (s << 3);
                unsigned bf0[8], bf1[8];
#pragma unroll
                for (int nt = 0; nt < 8; nt++) {
                    int cn = wn + (nt << 3) + gid;
                    bf0[nt] = Bs[cn][kloc + tig];
                    bf1[nt] = Bs[cn][kloc + tig + 4];
                }
                const int ks = s << 3;
#pragma unroll
                for (int mt = 0; mt < 2; mt++) {
                    int rl = wm + (mt << 4) + gid;
                    unsigned a0 = f2tf(As[cur][rl][ks + tig]);
                    unsigned a1 = f2tf(As[cur][rl + 8][ks + tig]);
                    unsigned a2 = f2tf(As[cur][rl][ks + tig + 4]);
                    unsigned a3 = f2tf(As[cur][rl + 8][ks + tig + 4]);
#pragma unroll
                    for (int nt = 0; nt < 8; nt++) {
                        asm volatile(
                            "mma.sync.aligned.m16n8k8.row.col.f32.tf32.tf32.f32 "
                            "{%0,%1,%2,%3}, {%4,%5,%6,%7}, {%8,%9}, {%0,%1,%2,%3};"
                            : "+f"(acc[mt][nt][0]), "+f"(acc[mt][nt][1]),
                              "+f"(acc[mt][nt][2]), "+f"(acc[mt][nt][3])
                            : "r"(a0), "r"(a1), "r"(a2), "r"(a3),
                              "r"(bf0[nt]), "r"(bf1[nt]));
                    }
                }
            }
            __syncthreads();
        }

        // write partials
#pragma unroll
        for (int mt = 0; mt < 2; mt++) {
            int rr = wm + (mt << 4) + gid;
#pragma unroll
            for (int nt = 0; nt < 8; nt++) {
                int cc = wn + (nt << 3) + (tig << 1);
                *(float2*)&Pbase[(size_t)rr * GS + cc] =
                    make_float2(acc[mt][nt][0], acc[mt][nt][1]);
                *(float2*)&Pbase[(size_t)(rr + 8) * GS + cc] =
                    make_float2(acc[mt][nt][2], acc[mt][nt][3]);
            }
        }

        barid++; gbar(barid * PB);

        // phase B: gate epilogue (distributed over all 144*256 threads)
#pragma unroll
        for (int j = 0; j < 2; j++) {
            int idx = bid * 256 + tid + j * (PB * 256);
            if (idx < NB2 * 192) {
                int b = idx / 192;
                int c = (idx - b * 192) << 2;
                float4 sr = make_float4(0, 0, 0, 0), sz = sr, sn = sr;
#pragma unroll
                for (int z = 0; z < KSPLIT; z++) {
                    const float* P = g_part + ((size_t)z * NB2 + b) * GS;
                    float4 pr = *(const float4*)(P + c);
                    float4 pz = *(const float4*)(P + 768 + c);
                    float4 pn = *(const float4*)(P + 1536 + c);
                    sr.x += pr.x; sr.y += pr.y; sr.z += pr.z; sr.w += pr.w;
                    sz.x += pz.x; sz.y += pz.y; sz.z += pz.z; sz.w += pz.w;
                    sn.x += pn.x; sn.y += pn.y; sn.z += pn.z; sn.w += pn.w;
                }
                float4 hp = *(const float4*)(seq + (size_t)b * T * HS + (size_t)(t - 1) * HS + c);
                float4 br = *(const float4*)(bhh + c);
                float4 bz = *(const float4*)(bhh + 768 + c);
                float4 bn = *(const float4*)(bhh + 1536 + c);
                const float* gip = gi + (size_t)b * T * GS + (size_t)t * GS;
                float4 ir  = *(const float4*)(gip + c);
                float4 iz  = *(const float4*)(gip + 768 + c);
                float4 inn = *(const float4*)(gip + 1536 + c);
                float4 h;
                {
                    float rg = 1.f / (1.f + expf(-(ir.x + sr.x + br.x)));
                    float zg = 1.f / (1.f + expf(-(iz.x + sz.x + bz.x)));
                    float ng = tanhf(inn.x + rg * (sn.x + bn.x));
                    h.x = (1.f - zg) * ng + zg * hp.x;
                }
                {
                    float rg = 1.f / (1.f + expf(-(ir.y + sr.y + br.y)));
                    float zg = 1.f / (1.f + expf(-(iz.y + sz.y + bz.y)));
                    float ng = tanhf(inn.y + rg * (sn.y + bn.y));
                    h.y = (1.f - zg) * ng + zg * hp.y;
                }
                {
                    float rg = 1.f / (1.f + expf(-(ir.z + sr.z + br.z)));
                    float zg = 1.f / (1.f + expf(-(iz.z + sz.z + bz.z)));
                    float ng = tanhf(inn.z + rg * (sn.z + bn.z));
                    h.z = (1.f - zg) * ng + zg * hp.z;
                }
                {
                    float rg = 1.f / (1.f + expf(-(ir.w + sr.w + br.w)));
                    float zg = 1.f / (1.f + expf(-(iz.w + sz.w + bz.w)));
                    float ng = tanhf(inn.w + rg * (sn.w + bn.w));
                    h.w = (1.f - zg) * ng + zg * hp.w;
                }
                *(float4*)(seq + (size_t)b * T * HS + (size_t)t * HS + c) = h;
            }
        }

        barid++; gbar(barid * PB);
    }
}
#define PERSIST_SMEM (128 * 196 * 4 + 2 * 128 * 36 * 4)

// ---------------- GRU t=0 epilogue ----------------
__global__ __launch_bounds__(256) void gru_epi0(
    const float* __restrict__ gi, int T,
    const float* __restrict__ bhh, float* __restrict__ seq)
{
    int idx = blockIdx.x * 256 + threadIdx.x;
    int b = idx / 192;
    int c = (idx - b * 192) << 2;

    float4 br = *(const float4*)(bhh + c);
    float4 bz = *(const float4*)(bhh + 768 + c);
    float4 bn = *(const float4*)(bhh + 1536 + c);
    const float* gip = gi + (size_t)b * T * GS;
    float4 ir  = *(const float4*)(gip + c);
    float4 iz  = *(const float4*)(gip + 768 + c);
    float4 inn = *(const float4*)(gip + 1536 + c);

    float4 h;
    { float r = 1.f/(1.f+expf(-(ir.x+br.x))); float z = 1.f/(1.f+expf(-(iz.x+bz.x)));
      h.x = (1.f-z)*tanhf(inn.x + r*bn.x); }
    { float r = 1.f/(1.f+expf(-(ir.y+br.y))); float z = 1.f/(1.f+expf(-(iz.y+bz.y)));
      h.y = (1.f-z)*tanhf(inn.y + r*bn.y); }
    { float r = 1.f/(1.f+expf(-(ir.z+br.z))); float z = 1.f/(1.f+expf(-(iz.z+bz.z)));
      h.z = (1.f-z)*tanhf(inn.z + r*bn.z); }
    { float r = 1.f/(1.f+expf(-(ir.w+br.w))); float z = 1.f/(1.f+expf(-(iz.w+bz.w)));
      h.w = (1.f-z)*tanhf(inn.w + r*bn.w); }
    *(float4*)(seq + (size_t)b * T * HS + c) = h;
}

// ---------------- text_embed ----------------
__global__ __launch_bounds__(192) void text_embed_k(const float* __restrict__ wdt,
                                                    const float* __restrict__ bdt)
{
    int j = blockIdx.x;
    int h4 = threadIdx.x;
    const float* base = g_te + (size_t)j * TT * HS + (h4 << 2);
    float4 acc = make_float4(bdt[0], bdt[0], bdt[0], bdt[0]);
    for (int t = 0; t < TT; t++) {
        float4 v = *(const float4*)(base + (size_t)t * HS);
        float w = wdt[t];
        acc.x = fmaf(v.x, w, acc.x); acc.y = fmaf(v.y, w, acc.y);
        acc.z = fmaf(v.z, w, acc.z); acc.w = fmaf(v.w, w, acc.w);
    }
    *(float4*)&g_temb[(size_t)j * HS + (h4 << 2)] = acc;
}

// ---------------- attention ----------------
__global__ __launch_bounds__(256) void attn_k(const float* __restrict__ wd3)
{
    __shared__ float cv[HS];
    __shared__ float tb[HS];
    __shared__ float sc[3][TSEG];
    int j = blockIdx.x;
    int tid = threadIdx.x;
    const float* rawj = g_raw + (size_t)j * TSEG * HS;

    for (int h = tid; h < HS; h += 256) {
        float s = 0.f;
        for (int t = 0; t < TSEG; t++) s += rawj[(size_t)t * HS + h];
        cv[h] = s * (1.f / TSEG);
        tb[h] = g_temb[(size_t)j * HS + h];
    }
    __syncthreads();

    int t = tid >> 3;
    int lane = tid & 7;
    float s1 = 0.f, s2 = 0.f, s3 = 0.f;
    if (t < TSEG) {
        const float* rp = rawj + (size_t)t * HS;
        for (int h = lane; h < HS; h += 8) {
            float v = rp[h];
            s1 = fmaf(v, tb[h], s1);
            s2 = fmaf(v, cv[h], s2);
            s3 = fmaf(v, wd3[h], s3);
        }
    }
#pragma unroll
    for (int o = 4; o; o >>= 1) {
        s1 += __shfl_down_sync(0xffffffffu, s1, o, 8);
        s2 += __shfl_down_sync(0xffffffffu, s2, o, 8);
        s3 += __shfl_down_sync(0xffffffffu, s3, o, 8);
    }
    if (t < TSEG && lane == 0) {
        sc[0][t] = s1; sc[1][t] = s2; sc[2][t] = s3;
        g_score3[j * TSEG + t] = s3;
    }
    __syncthreads();

    if (tid == 0) {
        float tot[TSEG];
        for (int q = 0; q < TSEG; q++) tot[q] = 0.f;
        for (int s = 0; s < 3; s++) {
            float mx = sc[s][0];
            for (int q = 1; q < TSEG; q++) mx = fmaxf(mx, sc[s][q]);
            float sum = 0.f;
            float e[TSEG];
            for (int q = 0; q < TSEG; q++) { e[q] = expf(sc[s][q] - mx); sum += e[q]; }
            float inv = 1.f / sum;
            for (int q = 0; q < TSEG; q++) tot[q] += e[q] * inv;
        }
        for (int q = 0; q < TSEG; q++) g_causal[j * TSEG + q] = tot[q];
    }
}

// ---------------- build fused sequence ----------------
__global__ __launch_bounds__(192) void build_x_k(
    const float* __restrict__ text, const float* __restrict__ pos_text,
    const float* __restrict__ wd2, const float* __restrict__ bd2)
{
    int t = blockIdx.x;
    int j = blockIdx.y;
    int h = threadIdx.x << 2;
    float4 v;
    if (t < TSEG) {
        float c = g_causal[j * TSEG + t];
        float4 r  = *(const float4*)&g_raw[(size_t)j * TSEG * HS + (size_t)t * HS + h];
        float4 w2 = *(const float4*)&wd2[h];
        float4 b2 = *(const float4*)&bd2[h];
        v.x = r.x * fmaf(c, w2.x, b2.x);
        v.y = r.y * fmaf(c, w2.y, b2.y);
        v.z = r.z * fmaf(c, w2.z, b2.z);
        v.w = r.w * fmaf(c, w2.w, b2.w);
    } else {
        int tt = t - TSEG;
        const float* src = (j < NB)
            ? text     + (size_t)j        * TT * HS + (size_t)tt * HS + h
            : pos_text + (size_t)(j - NB) * TT * HS + (size_t)tt * HS + h;
        v = *(const float4*)src;
    }
    *(float4*)&g_x[(size_t)j * TF * HS + (size_t)t * HS + h] = v;
}

// ---------------- feats ----------------
__global__ __launch_bounds__(192) void feats_k(const float* __restrict__ wc1,
                                               const float* __restrict__ bc1)
{
    int j = blockIdx.x;
    int h = threadIdx.x << 2;
    const float* base = g_xs + (size_t)j * TF * HS + h;
    float4 acc = make_float4(bc1[0], bc1[0], bc1[0], bc1[0]);
    for (int t = 0; t < TF; t++) {
        float4 v = *(const float4*)(base + (size_t)t * HS);
        float w = wc1[t];
        acc.x = fmaf(v.x, w, acc.x); acc.y = fmaf(v.y, w, acc.y);
        acc.z = fmaf(v.z, w, acc.z); acc.w = fmaf(v.w, w, acc.w);
    }
    acc.x = acc.x >= 0.f ? acc.x : 0.01f * acc.x;
    acc.y = acc.y >= 0.f ? acc.y : 0.01f * acc.y;
    acc.z = acc.z >= 0.f ? acc.z : 0.01f * acc.z;
    acc.w = acc.w >= 0.f ? acc.w : 0.01f * acc.w;
    *(float4*)&g_feats[(size_t)j * HS + h] = acc;
}

// ---------------- pred ----------------
__global__ __launch_bounds__(256) void pred_k(const float* __restrict__ wc2,
                                              const float* __restrict__ bc2,
                                              float* __restrict__ out)
{
    int j = blockIdx.x;
    int warp = threadIdx.x >> 5;
    int lane = threadIdx.x & 31;
    const float* f = g_feats + (size_t)j * HS;
    for (int o = warp; o < 20; o += 8) {
        const float* w = wc2 + (size_t)o * HS;
        float s = 0.f;
        for (int k = lane; k < HS; k += 32) s = fmaf(f[k], w[k], s);
#pragma unroll
        for (int d = 16; d; d >>= 1) s += __shfl_down_sync(0xffffffffu, s, d);
        if (lane == 0) out[j * 20 + o] = s + bc2[o];
    }
}

// ---------------- top-10 gather ----------------
__global__ __launch_bounds__(192) void topk_k()
{
    __shared__ int idxA[10], idxB[10];
    int b = blockIdx.x;
    int tid = threadIdx.x;
    if (tid < 2) {
        const float* sp = g_score3 + (size_t)(tid == 0 ? b : b + NB) * TSEG;
        float v[TSEG];
        for (int q = 0; q < TSEG; q++) v[q] = sp[q];
        int* dst = (tid == 0) ? idxA : idxB;
        for (int k = 0; k < 10; k++) {
            float best = -1e38f; int bi = 0;
            for (int q = 0; q < TSEG; q++)
                if (v[q] > best) { best = v[q]; bi = q; }
            dst[k] = bi;
            v[bi] = -1e38f;
        }
    }
    __syncthreads();
    int h = tid << 2;
    const float* A  = g_raw + (size_t)b * TSEG * HS + h;
    const float* Bm = g_raw + (size_t)(b + NB) * TSEG * HS + h;
    float4 sa = make_float4(0, 0, 0, 0), sb = make_float4(0, 0, 0, 0);
#pragma unroll
    for (int k = 0; k < 10; k++) {
        float4 a = *(const float4*)(A  + (size_t)idxA[k] * HS);
        float4 c = *(const float4*)(Bm + (size_t)idxB[k] * HS);
        sa.x += a.x; sa.y += a.y; sa.z += a.z; sa.w += a.w;
        sb.x += c.x; sb.y += c.y; sb.z += c.z; sb.w += c.w;
    }
    float4 d = make_float4((sa.x - sb.x) * 0.1f, (sa.y - sb.y) * 0.1f,
                           (sa.z - sb.z) * 0.1f, (sa.w - sb.w) * 0.1f);
    *(float4*)&g_diff[(size_t)b * HS + h] = d;
}

// ---------------- loss ----------------
__global__ __launch_bounds__(1024) void loss_k(float* __restrict__ out, int out_size)
{
    __shared__ float red[32];
    int tid = threadIdx.x;
    float s = 0.f;
    for (int i = tid; i < NB * HS; i += 1024) {
        float d = g_diffW[i];
        s = fmaf(d, d, s);
    }
#pragma unroll
    for (int d = 16; d; d >>= 1) s += __shfl_down_sync(0xffffffffu, s, d);
    if ((tid & 31) == 0) red[tid >> 5] = s;
    __syncthreads();
    if (tid < 32) {
        float v = red[tid];
#pragma unroll
        for (int d = 16; d; d >>= 1) v += __shfl_down_sync(0xffffffffu, v, d);
        if (tid == 0 && out_size > NB2 * 20)
            out[NB2 * 20] = v * (1.f / (NB * HS));
    }
}

// ---------------- host launcher ----------------
extern "C" void kernel_launch(void* const* d_in, const int* in_sizes, int n_in,
                              void* d_out, int out_size)
{
    const float* s3d      = (const float*)d_in[0];
    const float* text     = (const float*)d_in[1];
    const float* pos_s3d  = (const float*)d_in[2];
    const float* pos_text = (const float*)d_in[3];
    const float* W_lin1 = (const float*)d_in[4];
    const float* b_lin1 = (const float*)d_in[5];
    const float* Wih_t  = (const float*)d_in[6];
    const float* Whh_t  = (const float*)d_in[7];
    const float* bih_t  = (const float*)d_in[8];
    const float* bhh_t  = (const float*)d_in[9];
    const float* W_dt   = (const float*)d_in[10];
    const float* b_dt   = (const float*)d_in[11];
    const float* W_d3   = (const float*)d_in[12];
    const float* W_d2   = (const float*)d_in[14];
    const float* b_d2   = (const float*)d_in[15];
    const float* Wih_g  = (const float*)d_in[16];
    const float* Whh_g  = (const float*)d_in[17];
    const float* bih_g  = (const float*)d_in[18];
    const float* bhh_g  = (const float*)d_in[19];
    const float* W_c1   = (const float*)d_in[20];
    const float* b_c1   = (const float*)d_in[21];
    const float* W_c2   = (const float*)d_in[22];
    const float* b_c2   = (const float*)d_in[23];
    const float* W_d4   = (const float*)d_in[24];
    float* out = (float*)d_out;

    float *p_raw, *p_gi, *p_te, *p_x, *p_xs, *p_diff, *p_diffW;
    cudaGetSymbolAddress((void**)&p_raw,   g_raw);
    cudaGetSymbolAddress((void**)&p_gi,    g_gi);
    cudaGetSymbolAddress((void**)&p_te,    g_te);
    cudaGetSymbolAddress((void**)&p_x,     g_x);
    cudaGetSymbolAddress((void**)&p_xs,    g_xs);
    cudaGetSymbolAddress((void**)&p_diff,  g_diff);
    cudaGetSymbolAddress((void**)&p_diffW, g_diffW);

    // idempotent; no static guards allowed
    cudaFuncSetAttribute(gemm_tf32,   cudaFuncAttributeMaxDynamicSharedMemorySize, GEMM_SMEM);
    cudaFuncSetAttribute(gru_persist, cudaFuncAttributeMaxDynamicSharedMemorySize, PERSIST_SMEM);

    // 1) lin1: A and Bm into raw_img (M=3840 each, N=768, K=1024)
    gemm_tf32<<<dim3(6, 30), 128, GEMM_SMEM>>>(s3d,     1024, W_lin1, 1024, b_lin1, p_raw,              768, 1024);
    gemm_tf32<<<dim3(6, 30), 128, GEMM_SMEM>>>(pos_s3d, 1024, W_lin1, 1024, b_lin1, p_raw + 3840 * 768, 768, 1024);

    // 2) text GRU input projection (M=9344 each, N=2304, K=768)
    gemm_tf32<<<dim3(18, 73), 128, GEMM_SMEM>>>(text,     768, Wih_t, 768, bih_t, p_gi,                     GS, 768);
    gemm_tf32<<<dim3(18, 73), 128, GEMM_SMEM>>>(pos_text, 768, Wih_t, 768, bih_t, p_gi + (size_t)9344 * GS, GS, 768);

    // 3) text GRU: t=0 epilogue, then persistent kernel for t=1..72
    gru_epi0<<<192, 256>>>(p_gi, TT, bhh_t, p_te);
    zero_arrive_k<<<1, 1>>>();
    gru_persist<<<PB, 256, PERSIST_SMEM>>>(p_te, TT, Whh_t, p_gi, bhh_t);

    // 4) text_embed, attention, fused-sequence assembly
    text_embed_k<<<NB2, 192>>>(W_dt, b_dt);
    attn_k<<<NB2, 256>>>(W_d3);
    build_x_k<<<dim3(TF, NB2), 192>>>(text, pos_text, W_d2, b_d2);

    // 5) fusion GRU input projection (M=26368, N=2304, K=768)
    gemm_tf32<<<dim3(18, 206), 128, GEMM_SMEM>>>(p_x, 768, Wih_g, 768, bih_g, p_gi, GS, 768);

    // 6) fusion GRU: t=0 epilogue, then persistent kernel for t=1..102
    gru_epi0<<<192, 256>>>(p_gi, TF, bhh_g, p_xs);
    zero_arrive_k<<<1, 1>>>();
    gru_persist<<<PB, 256, PERSIST_SMEM>>>(p_xs, TF, Whh_g, p_gi, bhh_g);

    // 7) classifier
    feats_k<<<NB2, 192>>>(W_c1, b_c1);
    pred_k<<<NB2, 256>>>(W_c2, b_c2, out);

    // 8) top-10 gather + loss
    topk_k<<<NB, 192>>>();
    gemm_tf32<<<dim3(6, 1), 128, GEMM_SMEM>>>(p_diff, 768, W_d4, 768, nullptr, p_diffW, 768, 768);
    loss_k<<<1, 1024>>>(out, out_size);
}